// round 13
// baseline (speedup 1.0000x reference)
#include <cuda_runtime.h>
#include <cuda_fp16.h>
#include <cstdint>

// Problem constants
#define BB 8
#define NN 2048
#define FF 256
#define CHUNKS (NN / 64)

// Scratch (allocation-free rule: __device__ globals)
__device__ __half g_xh[BB * NN * FF];    // x in f16              8.4 MB
__device__ __half g_Wh[FF * FF];         // W in f16
__device__ __half g_hTh[BB * FF * NN];   // h f16, [b][f][n]      8.4 MB
__device__ float g_wsrc[FF];             // W^T a_src
__device__ float g_wdst[FF];             // W^T a_dst
__device__ float g_es1[BB * NN];         // exp(s_src)
__device__ float g_es2[BB * NN];         // exp(0.2*s_src)
__device__ uint32_t g_edEG[BB * NN];     // packed half2(e^s_dst, e^{.2 s_dst})

// ---------------------------------------------------------------------------
// helpers
// ---------------------------------------------------------------------------
__device__ __forceinline__ uint32_t smem_u32(const void* p) {
    uint32_t a;
    asm("{ .reg .u64 t; cvta.to.shared.u64 t, %1; cvt.u32.u64 %0, t; }"
        : "=r"(a) : "l"(p));
    return a;
}

__device__ __forceinline__ void cp16(uint32_t dst, const void* src) {
    asm volatile(
        "{ .reg .u64 g; cvta.to.global.u64 g, %1;"
        "  cp.async.cg.shared.global [%0], [g], 16; }"
        ::"r"(dst), "l"(src) : "memory");
}
#define CP_COMMIT() asm volatile("cp.async.commit_group;" ::: "memory")
#define CP_WAIT1() asm volatile("cp.async.wait_group 1;" ::: "memory")
#define CP_WAIT0() asm volatile("cp.async.wait_group 0;" ::: "memory")

__device__ __forceinline__ void ldsm4(uint32_t* r, uint32_t a) {
    asm volatile("ldmatrix.sync.aligned.m8n8.x4.shared.b16 {%0,%1,%2,%3}, [%4];"
                 : "=r"(r[0]), "=r"(r[1]), "=r"(r[2]), "=r"(r[3]) : "r"(a));
}

__device__ __forceinline__ void mma_f16(float* d, const uint32_t* a, uint32_t b0,
                                        uint32_t b1) {
    asm volatile(
        "mma.sync.aligned.m16n8k16.row.col.f32.f16.f16.f32 "
        "{%0,%1,%2,%3}, {%4,%5,%6,%7}, {%8,%9}, {%0,%1,%2,%3};"
        : "+f"(d[0]), "+f"(d[1]), "+f"(d[2]), "+f"(d[3])
        : "r"(a[0]), "r"(a[1]), "r"(a[2]), "r"(a[3]), "r"(b0), "r"(b1));
}

// tile row stride: 64 f16 + 8 pad = 144 bytes (9 x 16B -> conflict-free LDSM)
#define TSTRIDE 144

// ---------------------------------------------------------------------------
// wvec + cvt_w: w_src[k] = sum_o a_src[o]*W[o][k] (warp per k, 256 warps),
// plus f32->f16 conversion of W in the same kernel.
// ---------------------------------------------------------------------------
__global__ __launch_bounds__(256) void wvec_cvtw_kernel(const float* __restrict__ W,
                                                        const float* __restrict__ a_src,
                                                        const float* __restrict__ a_dst) {
    int t = threadIdx.x, lane = t & 31, warp = t >> 5;
    int k = blockIdx.x * 8 + warp;     // 0..255
    float s1 = 0.f, s2 = 0.f;
    #pragma unroll
    for (int q = 0; q < 8; q++) {
        int o = lane + 32 * q;
        float w = W[(size_t)o * FF + k];
        s1 += a_src[o] * w;
        s2 += a_dst[o] * w;
    }
    #pragma unroll
    for (int o = 16; o; o >>= 1) {
        s1 += __shfl_xor_sync(0xFFFFFFFFu, s1, o);
        s2 += __shfl_xor_sync(0xFFFFFFFFu, s2, o);
    }
    if (lane == 0) {
        g_wsrc[k] = s1;
        g_wdst[k] = s2;
    }
    const float4* src = reinterpret_cast<const float4*>(W);
    __half2* dst = reinterpret_cast<__half2*>(g_Wh);
    int gt = blockIdx.x * 256 + t;
    #pragma unroll
    for (int q = 0; q < 2; q++) {
        int i = gt + 8192 * q;
        float4 v = src[i];
        dst[i * 2] = __floats2half2_rn(v.x, v.y);
        dst[i * 2 + 1] = __floats2half2_rn(v.z, v.w);
    }
}

// ---------------------------------------------------------------------------
// score + cvt_x: s_src = x.w_src, s_dst = x.w_dst (warp per row), and emit
// the f16 copy of x while the row is in registers.
// ---------------------------------------------------------------------------
__global__ __launch_bounds__(256) void score_kernel(const float* __restrict__ x) {
    __shared__ float ws[FF], wd[FF];
    int t = threadIdx.x;
    ws[t] = g_wsrc[t];
    wd[t] = g_wdst[t];
    __syncthreads();
    int warp = t >> 5, lane = t & 31;
    int g = blockIdx.x * 8 + warp;
    const float4* xr = reinterpret_cast<const float4*>(x + (size_t)g * FF);
    __half2* xo = reinterpret_cast<__half2*>(g_xh + (size_t)g * FF);
    float s1 = 0.f, s2 = 0.f;
    #pragma unroll
    for (int q = 0; q < 2; q++) {
        int idx = lane + 32 * q;
        float4 v = xr[idx];
        xo[idx * 2] = __floats2half2_rn(v.x, v.y);
        xo[idx * 2 + 1] = __floats2half2_rn(v.z, v.w);
        float4 w1 = *reinterpret_cast<const float4*>(&ws[idx * 4]);
        float4 w2 = *reinterpret_cast<const float4*>(&wd[idx * 4]);
        s1 += v.x * w1.x + v.y * w1.y + v.z * w1.z + v.w * w1.w;
        s2 += v.x * w2.x + v.y * w2.y + v.z * w2.z + v.w * w2.w;
    }
    #pragma unroll
    for (int o = 16; o; o >>= 1) {
        s1 += __shfl_xor_sync(0xFFFFFFFFu, s1, o);
        s2 += __shfl_xor_sync(0xFFFFFFFFu, s2, o);
    }
    if (lane == 0) {
        g_es1[g] = __expf(s1);
        g_es2[g] = __expf(0.2f * s1);
        float e1 = __expf(s2), e2 = __expf(0.2f * s2);
        __half2 pk = __floats2half2_rn(e1, e2);
        g_edEG[g] = *reinterpret_cast<uint32_t*>(&pk);
    }
}

// ---------------------------------------------------------------------------
// gemm_h v2: h_T[b][f][n] = sum_k W[f][k] * x[b][n][k]  (f16 mma, f32 accum)
// CTA tile m64(f) x n128, 8 warps (2m x 4n), warp m32 x n32 -> acc 32 regs.
// smem 55.3 KB, 3 CTAs/SM; grid 512 -> one balanced wave, 24 warps/SM.
// ---------------------------------------------------------------------------
#define GH_SMEM ((2 * 64 + 2 * 128) * TSTRIDE)   // 55296 B
__global__ __launch_bounds__(256, 3) void gemm_h_kernel() {
    extern __shared__ char smraw[];
    uint32_t su = smem_u32(smraw);
    const uint32_t AB[2] = {su, su + 64 * TSTRIDE};
    const uint32_t XB[2] = {su + 2 * 64 * TSTRIDE,
                            su + 2 * 64 * TSTRIDE + 128 * TSTRIDE};

    int t = threadIdx.x, l = t & 31, w = t >> 5;
    int b = blockIdx.z, n0 = blockIdx.x * 128, m0 = blockIdx.y * 64;
    int mbase = (w & 1) * 32, nbase = (w >> 1) * 32;
    int a_row = (l & 7) + ((l & 8) ? 8 : 0);
    int a_k = (l & 16) ? 16 : 0;
    int b_row = (l & 7) + ((l & 16) ? 8 : 0);
    int b_k = (l & 8) ? 16 : 0;

    const __half* Wsrc = g_Wh + (size_t)m0 * FF;
    const __half* Xsrc = g_xh + ((size_t)b * NN + n0) * FF;

    float acc[2][4][4] = {};

    #define GH_FILL(kc, s)                                                   \
        do {                                                                 \
            _Pragma("unroll")                                                \
            for (int q = 0; q < 2; q++) {                                    \
                int e = t + 256 * q;                                         \
                int fr = e >> 3, sg = e & 7;                                 \
                cp16(AB[s] + fr * TSTRIDE + sg * 16,                         \
                     Wsrc + (size_t)fr * FF + (kc) + sg * 8);                \
            }                                                                \
            _Pragma("unroll")                                                \
            for (int q = 0; q < 4; q++) {                                    \
                int e = t + 256 * q;                                         \
                int fr = e >> 3, sg = e & 7;                                 \
                cp16(XB[s] + fr * TSTRIDE + sg * 16,                         \
                     Xsrc + (size_t)fr * FF + (kc) + sg * 8);                \
            }                                                                \
            CP_COMMIT();                                                     \
        } while (0)

    GH_FILL(0, 0);
    for (int c = 0; c < 4; c++) {
        int s = c & 1;
        if (c < 3) GH_FILL((c + 1) * 64, s ^ 1);
        if (c < 3) CP_WAIT1(); else CP_WAIT0();
        __syncthreads();
        #pragma unroll
        for (int kk = 0; kk < 4; kk++) {
            uint32_t bf[2][4];
            #pragma unroll
            for (int g = 0; g < 2; g++)
                ldsm4(bf[g], XB[s] + (nbase + g * 16 + b_row) * TSTRIDE +
                                 kk * 32 + b_k);
            #pragma unroll
            for (int mt = 0; mt < 2; mt++) {
                uint32_t a[4];
                ldsm4(a, AB[s] + (mbase + mt * 16 + a_row) * TSTRIDE +
                             kk * 32 + a_k);
                #pragma unroll
                for (int g = 0; g < 2; g++) {
                    mma_f16(acc[mt][2 * g], a, bf[g][0], bf[g][1]);
                    mma_f16(acc[mt][2 * g + 1], a, bf[g][2], bf[g][3]);
                }
            }
        }
        __syncthreads();
    }

    #pragma unroll
    for (int mt = 0; mt < 2; mt++) {
        int f = m0 + mbase + mt * 16 + (l >> 2);
        #pragma unroll
        for (int nt = 0; nt < 4; nt++) {
            int n = n0 + nbase + nt * 8 + 2 * (l & 3);
            *reinterpret_cast<__half2*>(&g_hTh[((size_t)b * FF + f) * NN + n]) =
                __floats2half2_rn(acc[mt][nt][0], acc[mt][nt][1]);
            *reinterpret_cast<__half2*>(&g_hTh[((size_t)b * FF + f + 8) * NN + n]) =
                __floats2half2_rn(acc[mt][nt][2], acc[mt][nt][3]);
        }
    }
}

// ---------------------------------------------------------------------------
// attn: fused masked softmax + alpha @ h, f16 mma.
// ITILE=64, 512 threads = 16 warps (2i x 8n), warp m32 x n32, 2 CTAs/SM.
// SINGLE sync per chunk, p buffer 3-deep, h buffer 2-deep:
//   PCOMP(c+1)->PB[(c+1)%3]; adj prefetch; CP_WAIT0; sync;
//   HFILL(c+1)->HB[(c+1)&1] (cp.async, fire-and-forget); mma(c).
// Every smem write is >=1 barrier away from its conflicting reads (PB depth 3,
// HB writer post-sync vs reader pre-sync). mma stays dense right after sync;
// fast warps roll into PCOMP(c+2) while slow warps finish mma(c).
// e^s_dst factors packed half2 in smem (halves LDS bytes + fits PB*3).
// ---------------------------------------------------------------------------
#define ITILE 64
#define PBSZ (64 * TSTRIDE)                         // 9216
#define HBSZ (256 * TSTRIDE)                        // 36864
#define OFF_P0 0                                    // 3 p buffers
#define OFF_H0 (3 * PBSZ)                           // 27648, 2 h buffers
#define OFF_SEG (OFF_H0 + 2 * HBSZ)                 // 101376, 8 KB
#define OFF_ES1 (OFF_SEG + NN * 4)                  // 109568
#define OFF_ES2 (OFF_ES1 + 256)
#define OFF_INVD (OFF_ES2 + 256)
#define AT_SMEM (OFF_INVD + 256)                    // 110336

__global__ __launch_bounds__(512, 2) void attn_kernel(const int* __restrict__ adj,
                                                      float* __restrict__ out) {
    extern __shared__ char smraw[];
    uint32_t su = smem_u32(smraw);
    uint32_t* sEG = reinterpret_cast<uint32_t*>(smraw + OFF_SEG);
    float* eS1 = reinterpret_cast<float*>(smraw + OFF_ES1);
    float* eS2 = reinterpret_cast<float*>(smraw + OFF_ES2);
    float* invd = reinterpret_cast<float*>(smraw + OFF_INVD);

    int t = threadIdx.x, l = t & 31, w = t >> 5;
    int b = blockIdx.y;
    int i0 = blockIdx.x * ITILE;

    for (int c = t; c < NN; c += 512) sEG[c] = g_edEG[b * NN + c];
    if (t < ITILE) {
        eS1[t] = g_es1[b * NN + i0 + t];
        eS2[t] = g_es2[b * NN + i0 + t];
    }
    __syncthreads();

    // p mapping: 8 threads/row, 8 j each (2 int4 adj quads, 4 uint2 factor lds)
    int pi = t >> 3, jq = t & 7;
    float E1 = eS1[pi], E2 = eS2[pi];
    const int4* adj_row = reinterpret_cast<const int4*>(
                              adj + ((size_t)b * NN + i0 + pi) * NN) + jq * 2;
    const uint2* sEG2 = reinterpret_cast<const uint2*>(sEG);
    float dreg = 0.f;

    // mma mapping: 2i x 8n warp grid, warp m32 x n32
    int mbase = (w & 1) * 32, nbase = (w >> 1) * 32;
    int a_row = (l & 7) + ((l & 8) ? 8 : 0);
    int a_k = (l & 16) ? 16 : 0;
    int b_row = (l & 7) + ((l & 16) ? 8 : 0);
    int b_k = (l & 8) ? 16 : 0;

    const __half* hsrc = g_hTh + (size_t)b * FF * NN;

    #define AT_HFILL(jc, hbase)                                              \
        do {                                                                 \
            _Pragma("unroll")                                                \
            for (int l2 = 0; l2 < 4; l2++) {                                 \
                int e = t + 512 * l2;                                        \
                int fr = e >> 3, sg = e & 7;                                 \
                cp16((hbase) + fr * TSTRIDE + sg * 16,                       \
                     hsrc + (size_t)fr * NN + (jc) + sg * 8);                \
            }                                                                \
            CP_COMMIT();                                                     \
        } while (0)

    #define PCOMP(jc, pbase)                                                 \
        do {                                                                 \
            uint32_t pk[4];                                                  \
            int jb2 = ((jc) >> 1) + jq * 4;                                  \
            _Pragma("unroll")                                                \
            for (int q = 0; q < 2; q++) {                                    \
                int4 av = aR[q];                                             \
                uint2 ua = sEG2[jb2 + q * 2];                                 \
                uint2 ub = sEG2[jb2 + q * 2 + 1];                             \
                float2 f0 = __half22float2(*reinterpret_cast<__half2*>(&ua.x)); \
                float2 f1 = __half22float2(*reinterpret_cast<__half2*>(&ua.y)); \
                float2 f2 = __half22float2(*reinterpret_cast<__half2*>(&ub.x)); \
                float2 f3 = __half22float2(*reinterpret_cast<__half2*>(&ub.y)); \
                float p0 = fmaxf(E1 * f0.x, E2 * f0.y);                      \
                float p1 = fmaxf(E1 * f1.x, E2 * f1.y);                      \
                float p2 = fmaxf(E1 * f2.x, E2 * f2.y);                      \
                float p3 = fmaxf(E1 * f3.x, E2 * f3.y);                      \
                p0 = av.x ? p0 : 0.f;                                        \
                p1 = av.y ? p1 : 0.f;                                        \
                p2 = av.z ? p2 : 0.f;                                        \
                p3 = av.w ? p3 : 0.f;                                        \
                __half2 h0 = __floats2half2_rn(p0, p1);                      \
                __half2 h1 = __floats2half2_rn(p2, p3);                      \
                float2 r0 = __half22float2(h0);                              \
                float2 r1 = __half22float2(h1);                              \
                dreg += (r0.x + r0.y) + (r1.x + r1.y);                       \
                pk[q * 2] = *reinterpret_cast<uint32_t*>(&h0);               \
                pk[q * 2 + 1] = *reinterpret_cast<uint32_t*>(&h1);           \
            }                                                                \
            uint32_t pa = (pbase) + pi * TSTRIDE + jq * 16;                  \
            asm volatile("st.shared.v4.b32 [%0], {%1,%2,%3,%4};" ::"r"(pa),  \
                         "r"(pk[0]), "r"(pk[1]), "r"(pk[2]), "r"(pk[3])      \
                         : "memory");                                        \
        } while (0)

    // prologue: p(0) -> PB0, h(0) -> HB0, adj for chunk 1
    int4 aR[2];
    aR[0] = adj_row[0];
    aR[1] = adj_row[1];
    PCOMP(0, su + OFF_P0);
    AT_HFILL(0, su + OFF_H0);
    aR[0] = adj_row[16];
    aR[1] = adj_row[17];

    float acc[2][4][4] = {};
    int pc = 0;   // PB index of chunk c

    for (int c = 0; c < CHUNKS; c++) {
        int pn = pc + 1;
        if (pn == 3) pn = 0;

        // producer for c+1 (PB[(c+1)%3]; no conflict with in-flight readers)
        if (c + 1 < CHUNKS) {
            PCOMP((c + 1) * 64, su + OFF_P0 + pn * PBSZ);
            if (c + 2 < CHUNKS) {
                aR[0] = adj_row[(c + 2) * 16];
                aR[1] = adj_row[(c + 2) * 16 + 1];
            }
        }

        CP_WAIT0();
        __syncthreads();

        // fire-and-forget h fill for c+1 into the buffer mma(c) does NOT read
        if (c + 1 < CHUNKS)
            AT_HFILL((c + 1) * 64, su + OFF_H0 + ((c + 1) & 1) * HBSZ);

        // ---- f16 tensor-core GEMM on PB[pc], HB[c&1] ----
        uint32_t pbase = su + OFF_P0 + pc * PBSZ;
        uint32_t hbase = su + OFF_H0 + (c & 1) * HBSZ;
        #pragma unroll
        for (int kk = 0; kk < 4; kk++) {
            uint32_t bf[2][4];
            #pragma unroll
            for (int g = 0; g < 2; g++)
                ldsm4(bf[g], hbase + (nbase + g * 16 + b_row) * TSTRIDE +
                                 kk * 32 + b_k);
            #pragma unroll
            for (int mt = 0; mt < 2; mt++) {
                uint32_t a[4];
                ldsm4(a, pbase + (mbase + mt * 16 + a_row) * TSTRIDE +
                             kk * 32 + a_k);
                #pragma unroll
                for (int g = 0; g < 2; g++) {
                    mma_f16(acc[mt][2 * g], a, bf[g][0], bf[g][1]);
                    mma_f16(acc[mt][2 * g + 1], a, bf[g][2], bf[g][3]);
                }
            }
        }
        pc = pn;
    }

    // ---- denominators (8 threads per row -> shfl over 3 levels) ----
    __syncthreads();   // all mma done before invd written over p-region? (invd
                       // is its own smem slot; sync just orders dreg->invd use)
    dreg += __shfl_xor_sync(0xFFFFFFFFu, dreg, 1);
    dreg += __shfl_xor_sync(0xFFFFFFFFu, dreg, 2);
    dreg += __shfl_xor_sync(0xFFFFFFFFu, dreg, 4);
    if ((t & 7) == 0) invd[pi] = (dreg > 0.f) ? (1.f / dreg) : 0.f;
    __syncthreads();

    // ---- epilogue ----
    #pragma unroll
    for (int mt = 0; mt < 2; mt++) {
        int lr = mbase + mt * 16 + (l >> 2);
        float s0 = invd[lr], s1v = invd[lr + 8];
        float* o0 = out + ((size_t)b * NN + i0 + lr) * FF + nbase;
        float* o1 = o0 + (size_t)8 * FF;
        #pragma unroll
        for (int nt = 0; nt < 4; nt++) {
            int cofs = nt * 8 + 2 * (l & 3);
            *reinterpret_cast<float2*>(o0 + cofs) =
                make_float2(acc[mt][nt][0] * s0, acc[mt][nt][1] * s0);
            *reinterpret_cast<float2*>(o1 + cofs) =
                make_float2(acc[mt][nt][2] * s1v, acc[mt][nt][3] * s1v);
        }
    }
}

// ---------------------------------------------------------------------------
extern "C" void kernel_launch(void* const* d_in, const int* in_sizes, int n_in,
                              void* d_out, int out_size) {
    const float* x     = (const float*)d_in[0];  // (B,N,F_in)
    const int*   adj   = (const int*)d_in[1];    // (B,N,N)
    const float* W     = (const float*)d_in[2];  // (F_out,F_in)
    const float* a_src = (const float*)d_in[3];  // (F_out)
    const float* a_dst = (const float*)d_in[4];  // (F_out)
    float* out = (float*)d_out;                  // (B,N,F_out)

    (void)in_sizes; (void)n_in; (void)out_size;

    // w = W^T a (warp-per-k) + W f16 conversion, one kernel
    wvec_cvtw_kernel<<<32, 256>>>(W, a_src, a_dst);
    // scores + x f16 conversion, one kernel
    score_kernel<<<(BB * NN) / 8, 256>>>(x);
    // h_T = W @ x^T (f16 tensor cores, m64xn128 tiles, 3 CTAs/SM)
    cudaFuncSetAttribute(gemm_h_kernel, cudaFuncAttributeMaxDynamicSharedMemorySize,
                         GH_SMEM);
    gemm_h_kernel<<<dim3(NN / 128, FF / 64, BB), 256, GH_SMEM>>>();
    // fused masked softmax + alpha @ h (single-sync, PB x3, 2 CTAs/SM)
    cudaFuncSetAttribute(attn_kernel, cudaFuncAttributeMaxDynamicSharedMemorySize,
                         AT_SMEM);
    attn_kernel<<<dim3(NN / ITILE, BB), 512, AT_SMEM>>>(adj, out);
}

// round 14
// speedup vs baseline: 1.2394x; 1.2394x over previous
#include <cuda_runtime.h>
#include <cuda_fp16.h>
#include <cstdint>

// Problem constants
#define BB 8
#define NN 2048
#define FF 256
#define CHUNKS (NN / 64)

// Scratch (allocation-free rule: __device__ globals)
__device__ __half g_xh[BB * NN * FF];    // x in f16              8.4 MB
__device__ __half g_Wh[FF * FF];         // W in f16
__device__ __half g_hTh[BB * FF * NN];   // h f16, [b][f][n]      8.4 MB
__device__ float g_wsrc[FF];             // W^T a_src
__device__ float g_wdst[FF];             // W^T a_dst
__device__ float g_es1[BB * NN];         // exp(s_src)
__device__ float g_es2[BB * NN];         // exp(0.2*s_src)
__device__ uint32_t g_edEG[BB * NN];     // packed half2(e^s_dst, e^{.2 s_dst})

// ---------------------------------------------------------------------------
// helpers
// ---------------------------------------------------------------------------
__device__ __forceinline__ uint32_t smem_u32(const void* p) {
    uint32_t a;
    asm("{ .reg .u64 t; cvta.to.shared.u64 t, %1; cvt.u32.u64 %0, t; }"
        : "=r"(a) : "l"(p));
    return a;
}

__device__ __forceinline__ void cp16(uint32_t dst, const void* src) {
    asm volatile(
        "{ .reg .u64 g; cvta.to.global.u64 g, %1;"
        "  cp.async.cg.shared.global [%0], [g], 16; }"
        ::"r"(dst), "l"(src) : "memory");
}
#define CP_COMMIT() asm volatile("cp.async.commit_group;" ::: "memory")
#define CP_WAIT1() asm volatile("cp.async.wait_group 1;" ::: "memory")
#define CP_WAIT0() asm volatile("cp.async.wait_group 0;" ::: "memory")

__device__ __forceinline__ void ldsm4(uint32_t* r, uint32_t a) {
    asm volatile("ldmatrix.sync.aligned.m8n8.x4.shared.b16 {%0,%1,%2,%3}, [%4];"
                 : "=r"(r[0]), "=r"(r[1]), "=r"(r[2]), "=r"(r[3]) : "r"(a));
}

__device__ __forceinline__ void mma_f16(float* d, const uint32_t* a, uint32_t b0,
                                        uint32_t b1) {
    asm volatile(
        "mma.sync.aligned.m16n8k16.row.col.f32.f16.f16.f32 "
        "{%0,%1,%2,%3}, {%4,%5,%6,%7}, {%8,%9}, {%0,%1,%2,%3};"
        : "+f"(d[0]), "+f"(d[1]), "+f"(d[2]), "+f"(d[3])
        : "r"(a[0]), "r"(a[1]), "r"(a[2]), "r"(a[3]), "r"(b0), "r"(b1));
}

// tile row stride: 64 f16 + 8 pad = 144 bytes (9 x 16B -> conflict-free LDSM)
#define TSTRIDE 144

// ---------------------------------------------------------------------------
// wvec + cvt_w: w_src[k] = sum_o a_src[o]*W[o][k] (warp per k, 256 warps),
// plus f32->f16 conversion of W in the same kernel.
// ---------------------------------------------------------------------------
__global__ __launch_bounds__(256) void wvec_cvtw_kernel(const float* __restrict__ W,
                                                        const float* __restrict__ a_src,
                                                        const float* __restrict__ a_dst) {
    int t = threadIdx.x, lane = t & 31, warp = t >> 5;
    int k = blockIdx.x * 8 + warp;     // 0..255
    float s1 = 0.f, s2 = 0.f;
    #pragma unroll
    for (int q = 0; q < 8; q++) {
        int o = lane + 32 * q;
        float w = W[(size_t)o * FF + k];
        s1 += a_src[o] * w;
        s2 += a_dst[o] * w;
    }
    #pragma unroll
    for (int o = 16; o; o >>= 1) {
        s1 += __shfl_xor_sync(0xFFFFFFFFu, s1, o);
        s2 += __shfl_xor_sync(0xFFFFFFFFu, s2, o);
    }
    if (lane == 0) {
        g_wsrc[k] = s1;
        g_wdst[k] = s2;
    }
    const float4* src = reinterpret_cast<const float4*>(W);
    __half2* dst = reinterpret_cast<__half2*>(g_Wh);
    int gt = blockIdx.x * 256 + t;
    #pragma unroll
    for (int q = 0; q < 2; q++) {
        int i = gt + 8192 * q;
        float4 v = src[i];
        dst[i * 2] = __floats2half2_rn(v.x, v.y);
        dst[i * 2 + 1] = __floats2half2_rn(v.z, v.w);
    }
}

// ---------------------------------------------------------------------------
// score + cvt_x: s_src = x.w_src, s_dst = x.w_dst (warp per row), and emit
// the f16 copy of x while the row is in registers.
// ---------------------------------------------------------------------------
__global__ __launch_bounds__(256) void score_kernel(const float* __restrict__ x) {
    __shared__ float ws[FF], wd[FF];
    int t = threadIdx.x;
    ws[t] = g_wsrc[t];
    wd[t] = g_wdst[t];
    __syncthreads();
    int warp = t >> 5, lane = t & 31;
    int g = blockIdx.x * 8 + warp;
    const float4* xr = reinterpret_cast<const float4*>(x + (size_t)g * FF);
    __half2* xo = reinterpret_cast<__half2*>(g_xh + (size_t)g * FF);
    float s1 = 0.f, s2 = 0.f;
    #pragma unroll
    for (int q = 0; q < 2; q++) {
        int idx = lane + 32 * q;
        float4 v = xr[idx];
        xo[idx * 2] = __floats2half2_rn(v.x, v.y);
        xo[idx * 2 + 1] = __floats2half2_rn(v.z, v.w);
        float4 w1 = *reinterpret_cast<const float4*>(&ws[idx * 4]);
        float4 w2 = *reinterpret_cast<const float4*>(&wd[idx * 4]);
        s1 += v.x * w1.x + v.y * w1.y + v.z * w1.z + v.w * w1.w;
        s2 += v.x * w2.x + v.y * w2.y + v.z * w2.z + v.w * w2.w;
    }
    #pragma unroll
    for (int o = 16; o; o >>= 1) {
        s1 += __shfl_xor_sync(0xFFFFFFFFu, s1, o);
        s2 += __shfl_xor_sync(0xFFFFFFFFu, s2, o);
    }
    if (lane == 0) {
        g_es1[g] = __expf(s1);
        g_es2[g] = __expf(0.2f * s1);
        float e1 = __expf(s2), e2 = __expf(0.2f * s2);
        __half2 pk = __floats2half2_rn(e1, e2);
        g_edEG[g] = *reinterpret_cast<uint32_t*>(&pk);
    }
}

// ---------------------------------------------------------------------------
// gemm_h v2: h_T[b][f][n] = sum_k W[f][k] * x[b][n][k]  (f16 mma, f32 accum)
// CTA tile m64(f) x n128, 8 warps (2m x 4n), warp m32 x n32 -> acc 32 regs.
// smem 55.3 KB, 3 CTAs/SM; grid 512 -> one balanced wave, 24 warps/SM.
// ---------------------------------------------------------------------------
#define GH_SMEM ((2 * 64 + 2 * 128) * TSTRIDE)   // 55296 B
__global__ __launch_bounds__(256, 3) void gemm_h_kernel() {
    extern __shared__ char smraw[];
    uint32_t su = smem_u32(smraw);
    const uint32_t AB[2] = {su, su + 64 * TSTRIDE};
    const uint32_t XB[2] = {su + 2 * 64 * TSTRIDE,
                            su + 2 * 64 * TSTRIDE + 128 * TSTRIDE};

    int t = threadIdx.x, l = t & 31, w = t >> 5;
    int b = blockIdx.z, n0 = blockIdx.x * 128, m0 = blockIdx.y * 64;
    int mbase = (w & 1) * 32, nbase = (w >> 1) * 32;
    int a_row = (l & 7) + ((l & 8) ? 8 : 0);
    int a_k = (l & 16) ? 16 : 0;
    int b_row = (l & 7) + ((l & 16) ? 8 : 0);
    int b_k = (l & 8) ? 16 : 0;

    const __half* Wsrc = g_Wh + (size_t)m0 * FF;
    const __half* Xsrc = g_xh + ((size_t)b * NN + n0) * FF;

    float acc[2][4][4] = {};

    #define GH_FILL(kc, s)                                                   \
        do {                                                                 \
            _Pragma("unroll")                                                \
            for (int q = 0; q < 2; q++) {                                    \
                int e = t + 256 * q;                                         \
                int fr = e >> 3, sg = e & 7;                                 \
                cp16(AB[s] + fr * TSTRIDE + sg * 16,                         \
                     Wsrc + (size_t)fr * FF + (kc) + sg * 8);                \
            }                                                                \
            _Pragma("unroll")                                                \
            for (int q = 0; q < 4; q++) {                                    \
                int e = t + 256 * q;                                         \
                int fr = e >> 3, sg = e & 7;                                 \
                cp16(XB[s] + fr * TSTRIDE + sg * 16,                         \
                     Xsrc + (size_t)fr * FF + (kc) + sg * 8);                \
            }                                                                \
            CP_COMMIT();                                                     \
        } while (0)

    GH_FILL(0, 0);
    for (int c = 0; c < 4; c++) {
        int s = c & 1;
        if (c < 3) GH_FILL((c + 1) * 64, s ^ 1);
        if (c < 3) CP_WAIT1(); else CP_WAIT0();
        __syncthreads();
        #pragma unroll
        for (int kk = 0; kk < 4; kk++) {
            uint32_t bf[2][4];
            #pragma unroll
            for (int g = 0; g < 2; g++)
                ldsm4(bf[g], XB[s] + (nbase + g * 16 + b_row) * TSTRIDE +
                                 kk * 32 + b_k);
            #pragma unroll
            for (int mt = 0; mt < 2; mt++) {
                uint32_t a[4];
                ldsm4(a, AB[s] + (mbase + mt * 16 + a_row) * TSTRIDE +
                             kk * 32 + a_k);
                #pragma unroll
                for (int g = 0; g < 2; g++) {
                    mma_f16(acc[mt][2 * g], a, bf[g][0], bf[g][1]);
                    mma_f16(acc[mt][2 * g + 1], a, bf[g][2], bf[g][3]);
                }
            }
        }
        __syncthreads();
    }

    #pragma unroll
    for (int mt = 0; mt < 2; mt++) {
        int f = m0 + mbase + mt * 16 + (l >> 2);
        #pragma unroll
        for (int nt = 0; nt < 4; nt++) {
            int n = n0 + nbase + nt * 8 + 2 * (l & 3);
            *reinterpret_cast<__half2*>(&g_hTh[((size_t)b * FF + f) * NN + n]) =
                __floats2half2_rn(acc[mt][nt][0], acc[mt][nt][1]);
            *reinterpret_cast<__half2*>(&g_hTh[((size_t)b * FF + f + 8) * NN + n]) =
                __floats2half2_rn(acc[mt][nt][2], acc[mt][nt][3]);
        }
    }
}

// ---------------------------------------------------------------------------
// attn: fused masked softmax + alpha @ h, f16 mma.  R12-EXACT structure
// (best measured): ITILE=64, 512 threads = 16 warps (2i x 8n), warp m32xn32,
// 2 CTAs/SM, TWO-sync pipeline:
//   p(c) -> adj prefetch -> HFILL(c+1) -> WAIT1 -> sync -> mma(c) -> sync.
// Only change vs R12: e^s_dst factors packed half2 in smem (halves PCOMP LDS
// bytes, -8 KB smem; isolated ingredient from R13, numerically validated).
// p = adj * max(e^s_src * e^s_dst, e^{.2 s_src} * e^{.2 s_dst})  (exact lrelu)
// ---------------------------------------------------------------------------
#define ITILE 64
#define PBSZ (64 * TSTRIDE)                         // 9216
#define HBSZ (256 * TSTRIDE)                        // 36864
#define OFF_P0 0
#define OFF_P1 PBSZ
#define OFF_H0 (2 * PBSZ)                           // 18432
#define OFF_H1 (OFF_H0 + HBSZ)                      // 55296
#define OFF_SEG (OFF_H1 + HBSZ)                     // 92160, 8 KB packed
#define OFF_ES1 (OFF_SEG + NN * 4)                  // 100352
#define OFF_ES2 (OFF_ES1 + 256)
#define OFF_INVD (OFF_ES2 + 256)
#define AT_SMEM (OFF_INVD + 256)                    // 101120

__global__ __launch_bounds__(512, 2) void attn_kernel(const int* __restrict__ adj,
                                                      float* __restrict__ out) {
    extern __shared__ char smraw[];
    uint32_t su = smem_u32(smraw);
    uint32_t* sEG = reinterpret_cast<uint32_t*>(smraw + OFF_SEG);
    float* eS1 = reinterpret_cast<float*>(smraw + OFF_ES1);
    float* eS2 = reinterpret_cast<float*>(smraw + OFF_ES2);
    float* invd = reinterpret_cast<float*>(smraw + OFF_INVD);

    int t = threadIdx.x, l = t & 31, w = t >> 5;
    int b = blockIdx.y;
    int i0 = blockIdx.x * ITILE;

    for (int c = t; c < NN; c += 512) sEG[c] = g_edEG[b * NN + c];
    if (t < ITILE) {
        eS1[t] = g_es1[b * NN + i0 + t];
        eS2[t] = g_es2[b * NN + i0 + t];
    }
    __syncthreads();

    // p mapping: 8 threads/row, 8 j each (2 int4 adj quads, 4 uint2 factors)
    int pi = t >> 3, jq = t & 7;
    float E1 = eS1[pi], E2 = eS2[pi];
    const int4* adj_row = reinterpret_cast<const int4*>(
                              adj + ((size_t)b * NN + i0 + pi) * NN) + jq * 2;
    const uint2* sEG2 = reinterpret_cast<const uint2*>(sEG);
    float dreg = 0.f;

    // mma mapping: 2i x 8n warp grid, warp m32 x n32
    int mbase = (w & 1) * 32, nbase = (w >> 1) * 32;
    int a_row = (l & 7) + ((l & 8) ? 8 : 0);
    int a_k = (l & 16) ? 16 : 0;
    int b_row = (l & 7) + ((l & 16) ? 8 : 0);
    int b_k = (l & 8) ? 16 : 0;

    const __half* hsrc = g_hTh + (size_t)b * FF * NN;

    const uint32_t PB[2] = {su + OFF_P0, su + OFF_P1};
    const uint32_t HB[2] = {su + OFF_H0, su + OFF_H1};

    #define AT_HFILL(jc, s)                                                  \
        do {                                                                 \
            _Pragma("unroll")                                                \
            for (int l2 = 0; l2 < 4; l2++) {                                 \
                int e = t + 512 * l2;                                        \
                int fr = e >> 3, sg = e & 7;                                 \
                cp16(HB[s] + fr * TSTRIDE + sg * 16,                         \
                     hsrc + (size_t)fr * NN + (jc) + sg * 8);                \
            }                                                                \
            CP_COMMIT();                                                     \
        } while (0)

    int4 aR[2];
    aR[0] = adj_row[0];
    aR[1] = adj_row[1];
    AT_HFILL(0, 0);

    float acc[2][4][4] = {};

    for (int c = 0; c < CHUNKS; c++) {
        int s = c & 1;
        int jc = c * 64;

        // ---- p(c) from prefetched adj regs (packed factor loads) ----
        {
            uint32_t pk[4];
            int jb2 = (jc >> 1) + jq * 4;   // uint2 index (pairs of packed u32)
            #pragma unroll
            for (int q = 0; q < 2; q++) {
                int4 av = aR[q];
                uint2 ua = sEG2[jb2 + q * 2];
                uint2 ub = sEG2[jb2 + q * 2 + 1];
                float2 f0 = __half22float2(*reinterpret_cast<__half2*>(&ua.x));
                float2 f1 = __half22float2(*reinterpret_cast<__half2*>(&ua.y));
                float2 f2 = __half22float2(*reinterpret_cast<__half2*>(&ub.x));
                float2 f3 = __half22float2(*reinterpret_cast<__half2*>(&ub.y));
                float p0 = fmaxf(E1 * f0.x, E2 * f0.y);
                float p1 = fmaxf(E1 * f1.x, E2 * f1.y);
                float p2 = fmaxf(E1 * f2.x, E2 * f2.y);
                float p3 = fmaxf(E1 * f3.x, E2 * f3.y);
                p0 = av.x ? p0 : 0.f;
                p1 = av.y ? p1 : 0.f;
                p2 = av.z ? p2 : 0.f;
                p3 = av.w ? p3 : 0.f;
                __half2 h0 = __floats2half2_rn(p0, p1);
                __half2 h1 = __floats2half2_rn(p2, p3);
                float2 r0 = __half22float2(h0);
                float2 r1 = __half22float2(h1);
                dreg += (r0.x + r0.y) + (r1.x + r1.y);
                pk[q * 2] = *reinterpret_cast<uint32_t*>(&h0);
                pk[q * 2 + 1] = *reinterpret_cast<uint32_t*>(&h1);
            }
            uint32_t pa = PB[s] + pi * TSTRIDE + jq * 16;
            asm volatile("st.shared.v4.b32 [%0], {%1,%2,%3,%4};" ::"r"(pa),
                         "r"(pk[0]), "r"(pk[1]), "r"(pk[2]), "r"(pk[3]) : "memory");
        }
        // ---- prefetch adj(c+1), issue h(c+1) cp.async ----
        if (c + 1 < CHUNKS) {
            aR[0] = adj_row[(c + 1) * 16];
            aR[1] = adj_row[(c + 1) * 16 + 1];
            AT_HFILL(jc + 64, s ^ 1);
            CP_WAIT1();
        } else {
            CP_WAIT0();
        }
        __syncthreads();

        // ---- f16 tensor-core GEMM on buffers s ----
        #pragma unroll
        for (int kk = 0; kk < 4; kk++) {
            uint32_t bf[2][4];
            #pragma unroll
            for (int g = 0; g < 2; g++)
                ldsm4(bf[g], HB[s] + (nbase + g * 16 + b_row) * TSTRIDE +
                                 kk * 32 + b_k);
            #pragma unroll
            for (int mt = 0; mt < 2; mt++) {
                uint32_t a[4];
                ldsm4(a, PB[s] + (mbase + mt * 16 + a_row) * TSTRIDE +
                             kk * 32 + a_k);
                #pragma unroll
                for (int g = 0; g < 2; g++) {
                    mma_f16(acc[mt][2 * g], a, bf[g][0], bf[g][1]);
                    mma_f16(acc[mt][2 * g + 1], a, bf[g][2], bf[g][3]);
                }
            }
        }
        __syncthreads();
    }

    // ---- denominators (8 threads per row -> shfl over 3 levels) ----
    dreg += __shfl_xor_sync(0xFFFFFFFFu, dreg, 1);
    dreg += __shfl_xor_sync(0xFFFFFFFFu, dreg, 2);
    dreg += __shfl_xor_sync(0xFFFFFFFFu, dreg, 4);
    if ((t & 7) == 0) invd[pi] = (dreg > 0.f) ? (1.f / dreg) : 0.f;
    __syncthreads();

    // ---- epilogue ----
    #pragma unroll
    for (int mt = 0; mt < 2; mt++) {
        int lr = mbase + mt * 16 + (l >> 2);
        float s0 = invd[lr], s1v = invd[lr + 8];
        float* o0 = out + ((size_t)b * NN + i0 + lr) * FF + nbase;
        float* o1 = o0 + (size_t)8 * FF;
        #pragma unroll
        for (int nt = 0; nt < 4; nt++) {
            int cofs = nt * 8 + 2 * (l & 3);
            *reinterpret_cast<float2*>(o0 + cofs) =
                make_float2(acc[mt][nt][0] * s0, acc[mt][nt][1] * s0);
            *reinterpret_cast<float2*>(o1 + cofs) =
                make_float2(acc[mt][nt][2] * s1v, acc[mt][nt][3] * s1v);
        }
    }
}

// ---------------------------------------------------------------------------
extern "C" void kernel_launch(void* const* d_in, const int* in_sizes, int n_in,
                              void* d_out, int out_size) {
    const float* x     = (const float*)d_in[0];  // (B,N,F_in)
    const int*   adj   = (const int*)d_in[1];    // (B,N,N)
    const float* W     = (const float*)d_in[2];  // (F_out,F_in)
    const float* a_src = (const float*)d_in[3];  // (F_out)
    const float* a_dst = (const float*)d_in[4];  // (F_out)
    float* out = (float*)d_out;                  // (B,N,F_out)

    (void)in_sizes; (void)n_in; (void)out_size;

    // w = W^T a (warp-per-k) + W f16 conversion, one kernel
    wvec_cvtw_kernel<<<32, 256>>>(W, a_src, a_dst);
    // scores + x f16 conversion, one kernel
    score_kernel<<<(BB * NN) / 8, 256>>>(x);
    // h_T = W @ x^T (f16 tensor cores, m64xn128 tiles, 3 CTAs/SM)
    cudaFuncSetAttribute(gemm_h_kernel, cudaFuncAttributeMaxDynamicSharedMemorySize,
                         GH_SMEM);
    gemm_h_kernel<<<dim3(NN / 128, FF / 64, BB), 256, GH_SMEM>>>();
    // fused masked softmax + alpha @ h (R12-exact two-sync, packed factors)
    cudaFuncSetAttribute(attn_kernel, cudaFuncAttributeMaxDynamicSharedMemorySize,
                         AT_SMEM);
    attn_kernel<<<dim3(NN / ITILE, BB), 512, AT_SMEM>>>(adj, out);
}

// round 15
// speedup vs baseline: 1.3078x; 1.0552x over previous
#include <cuda_runtime.h>
#include <cuda_fp16.h>
#include <cstdint>

// Problem constants
#define BB 8
#define NN 2048
#define FF 256
#define CHUNKS (NN / 64)

// Scratch (allocation-free rule: __device__ globals)
__device__ __half g_xh[BB * NN * FF];    // x in f16              8.4 MB
__device__ __half g_Wh[FF * FF];         // W in f16
__device__ __half g_hTh[BB * FF * NN];   // h f16, [b][f][n]      8.4 MB
__device__ float g_wsrc[FF];             // W^T a_src
__device__ float g_wdst[FF];             // W^T a_dst
__device__ float g_es1[BB * NN];         // exp(s_src)
__device__ float g_es2[BB * NN];         // exp(0.2*s_src)
__device__ uint32_t g_edEG[BB * NN];     // packed half2(e^s_dst, e^{.2 s_dst})

// ---------------------------------------------------------------------------
// helpers
// ---------------------------------------------------------------------------
__device__ __forceinline__ uint32_t smem_u32(const void* p) {
    uint32_t a;
    asm("{ .reg .u64 t; cvta.to.shared.u64 t, %1; cvt.u32.u64 %0, t; }"
        : "=r"(a) : "l"(p));
    return a;
}

__device__ __forceinline__ void cp16(uint32_t dst, const void* src) {
    asm volatile(
        "{ .reg .u64 g; cvta.to.global.u64 g, %1;"
        "  cp.async.cg.shared.global [%0], [g], 16; }"
        ::"r"(dst), "l"(src) : "memory");
}
#define CP_COMMIT() asm volatile("cp.async.commit_group;" ::: "memory")
#define CP_WAIT1() asm volatile("cp.async.wait_group 1;" ::: "memory")
#define CP_WAIT0() asm volatile("cp.async.wait_group 0;" ::: "memory")

__device__ __forceinline__ void ldsm4(uint32_t* r, uint32_t a) {
    asm volatile("ldmatrix.sync.aligned.m8n8.x4.shared.b16 {%0,%1,%2,%3}, [%4];"
                 : "=r"(r[0]), "=r"(r[1]), "=r"(r[2]), "=r"(r[3]) : "r"(a));
}

__device__ __forceinline__ void mma_f16(float* d, const uint32_t* a, uint32_t b0,
                                        uint32_t b1) {
    asm volatile(
        "mma.sync.aligned.m16n8k16.row.col.f32.f16.f16.f32 "
        "{%0,%1,%2,%3}, {%4,%5,%6,%7}, {%8,%9}, {%0,%1,%2,%3};"
        : "+f"(d[0]), "+f"(d[1]), "+f"(d[2]), "+f"(d[3])
        : "r"(a[0]), "r"(a[1]), "r"(a[2]), "r"(a[3]), "r"(b0), "r"(b1));
}

// tile row stride: 64 f16 + 8 pad = 144 bytes (9 x 16B -> conflict-free LDSM)
#define TSTRIDE 144

// ---------------------------------------------------------------------------
// wvec + cvt_w: w_src[k] = sum_o a_src[o]*W[o][k] (warp per k, 256 warps),
// plus f32->f16 conversion of W in the same kernel.
// ---------------------------------------------------------------------------
__global__ __launch_bounds__(256) void wvec_cvtw_kernel(const float* __restrict__ W,
                                                        const float* __restrict__ a_src,
                                                        const float* __restrict__ a_dst) {
    int t = threadIdx.x, lane = t & 31, warp = t >> 5;
    int k = blockIdx.x * 8 + warp;     // 0..255
    float s1 = 0.f, s2 = 0.f;
    #pragma unroll
    for (int q = 0; q < 8; q++) {
        int o = lane + 32 * q;
        float w = W[(size_t)o * FF + k];
        s1 += a_src[o] * w;
        s2 += a_dst[o] * w;
    }
    #pragma unroll
    for (int o = 16; o; o >>= 1) {
        s1 += __shfl_xor_sync(0xFFFFFFFFu, s1, o);
        s2 += __shfl_xor_sync(0xFFFFFFFFu, s2, o);
    }
    if (lane == 0) {
        g_wsrc[k] = s1;
        g_wdst[k] = s2;
    }
    const float4* src = reinterpret_cast<const float4*>(W);
    __half2* dst = reinterpret_cast<__half2*>(g_Wh);
    int gt = blockIdx.x * 256 + t;
    #pragma unroll
    for (int q = 0; q < 2; q++) {
        int i = gt + 8192 * q;
        float4 v = src[i];
        dst[i * 2] = __floats2half2_rn(v.x, v.y);
        dst[i * 2 + 1] = __floats2half2_rn(v.z, v.w);
    }
}

// ---------------------------------------------------------------------------
// score + cvt_x: s_src = x.w_src, s_dst = x.w_dst (warp per row), and emit
// the f16 copy of x while the row is in registers.
// ---------------------------------------------------------------------------
__global__ __launch_bounds__(256) void score_kernel(const float* __restrict__ x) {
    __shared__ float ws[FF], wd[FF];
    int t = threadIdx.x;
    ws[t] = g_wsrc[t];
    wd[t] = g_wdst[t];
    __syncthreads();
    int warp = t >> 5, lane = t & 31;
    int g = blockIdx.x * 8 + warp;
    const float4* xr = reinterpret_cast<const float4*>(x + (size_t)g * FF);
    __half2* xo = reinterpret_cast<__half2*>(g_xh + (size_t)g * FF);
    float s1 = 0.f, s2 = 0.f;
    #pragma unroll
    for (int q = 0; q < 2; q++) {
        int idx = lane + 32 * q;
        float4 v = xr[idx];
        xo[idx * 2] = __floats2half2_rn(v.x, v.y);
        xo[idx * 2 + 1] = __floats2half2_rn(v.z, v.w);
        float4 w1 = *reinterpret_cast<const float4*>(&ws[idx * 4]);
        float4 w2 = *reinterpret_cast<const float4*>(&wd[idx * 4]);
        s1 += v.x * w1.x + v.y * w1.y + v.z * w1.z + v.w * w1.w;
        s2 += v.x * w2.x + v.y * w2.y + v.z * w2.z + v.w * w2.w;
    }
    #pragma unroll
    for (int o = 16; o; o >>= 1) {
        s1 += __shfl_xor_sync(0xFFFFFFFFu, s1, o);
        s2 += __shfl_xor_sync(0xFFFFFFFFu, s2, o);
    }
    if (lane == 0) {
        g_es1[g] = __expf(s1);
        g_es2[g] = __expf(0.2f * s1);
        float e1 = __expf(s2), e2 = __expf(0.2f * s2);
        __half2 pk = __floats2half2_rn(e1, e2);
        g_edEG[g] = *reinterpret_cast<uint32_t*>(&pk);
    }
}

// ---------------------------------------------------------------------------
// gemm_h v3: h_T[b][f][n] = sum_k W[f][k] * x[b][n][k]  (f16 mma, f32 accum)
// CTA tile m128(f) x n128, 512 threads = 16 warps (4m x 4n), warp m32 x n32.
// smem 73.7 KB, 2 CTAs/SM via 64-reg cap; grid 256 <= 296 slots -> ONE wave
// (fixes the 1.15-wave tail of the 512-CTA shape).
// ---------------------------------------------------------------------------
#define GH_SMEM (4 * 128 * TSTRIDE)   // A0,A1,X0,X1 each 128*144 = 73728 B
__global__ __launch_bounds__(512, 2) void gemm_h_kernel() {
    extern __shared__ char smraw[];
    uint32_t su = smem_u32(smraw);
    const uint32_t AB[2] = {su, su + 128 * TSTRIDE};
    const uint32_t XB[2] = {su + 2 * 128 * TSTRIDE, su + 3 * 128 * TSTRIDE};

    int t = threadIdx.x, l = t & 31, w = t >> 5;
    int b = blockIdx.z, n0 = blockIdx.x * 128, m0 = blockIdx.y * 128;
    int mbase = (w & 3) * 32, nbase = (w >> 2) * 32;
    int a_row = (l & 7) + ((l & 8) ? 8 : 0);
    int a_k = (l & 16) ? 16 : 0;
    int b_row = (l & 7) + ((l & 16) ? 8 : 0);
    int b_k = (l & 8) ? 16 : 0;

    const __half* Wsrc = g_Wh + (size_t)m0 * FF;
    const __half* Xsrc = g_xh + ((size_t)b * NN + n0) * FF;

    float acc[2][4][4] = {};

    // A: 128 rows x 8 segs = 1024 cp16 (2/thread); X: same (2/thread)
    #define GH_FILL(kc, s)                                                   \
        do {                                                                 \
            _Pragma("unroll")                                                \
            for (int q = 0; q < 2; q++) {                                    \
                int e = t + 512 * q;                                         \
                int fr = e >> 3, sg = e & 7;                                 \
                cp16(AB[s] + fr * TSTRIDE + sg * 16,                         \
                     Wsrc + (size_t)fr * FF + (kc) + sg * 8);                \
                cp16(XB[s] + fr * TSTRIDE + sg * 16,                         \
                     Xsrc + (size_t)fr * FF + (kc) + sg * 8);                \
            }                                                                \
            CP_COMMIT();                                                     \
        } while (0)

    GH_FILL(0, 0);
    for (int c = 0; c < 4; c++) {
        int s = c & 1;
        if (c < 3) GH_FILL((c + 1) * 64, s ^ 1);
        if (c < 3) CP_WAIT1(); else CP_WAIT0();
        __syncthreads();
        #pragma unroll
        for (int kk = 0; kk < 4; kk++) {
            uint32_t bf[2][4];
            #pragma unroll
            for (int g = 0; g < 2; g++)
                ldsm4(bf[g], XB[s] + (nbase + g * 16 + b_row) * TSTRIDE +
                                 kk * 32 + b_k);
            #pragma unroll
            for (int mt = 0; mt < 2; mt++) {
                uint32_t a[4];
                ldsm4(a, AB[s] + (mbase + mt * 16 + a_row) * TSTRIDE +
                             kk * 32 + a_k);
                #pragma unroll
                for (int g = 0; g < 2; g++) {
                    mma_f16(acc[mt][2 * g], a, bf[g][0], bf[g][1]);
                    mma_f16(acc[mt][2 * g + 1], a, bf[g][2], bf[g][3]);
                }
            }
        }
        __syncthreads();
    }

    #pragma unroll
    for (int mt = 0; mt < 2; mt++) {
        int f = m0 + mbase + mt * 16 + (l >> 2);
        #pragma unroll
        for (int nt = 0; nt < 4; nt++) {
            int n = n0 + nbase + nt * 8 + 2 * (l & 3);
            *reinterpret_cast<__half2*>(&g_hTh[((size_t)b * FF + f) * NN + n]) =
                __floats2half2_rn(acc[mt][nt][0], acc[mt][nt][1]);
            *reinterpret_cast<__half2*>(&g_hTh[((size_t)b * FF + f + 8) * NN + n]) =
                __floats2half2_rn(acc[mt][nt][2], acc[mt][nt][3]);
        }
    }
}

// ---------------------------------------------------------------------------
// attn: fused masked softmax + alpha @ h, f16 mma.  R14 structure (best
// measured) with ONE ordering-safe micro-change: HFILL(c+1) is issued BEFORE
// PCOMP(c) so the cp.async group gets ~PCOMP-duration more flight time.
// Barrier/buffer semantics identical (HB[s^1]'s last reader finished before
// the previous trailing sync; WAIT1 still gates on group(c) from last chunk).
// ITILE=64, 512 threads = 16 warps (2i x 8n), warp m32 x n32, 2 CTAs/SM,
// two-sync pipeline; e^s_dst factors packed half2 in smem.
// p = adj * max(e^s_src * e^s_dst, e^{.2 s_src} * e^{.2 s_dst})  (exact lrelu)
// ---------------------------------------------------------------------------
#define ITILE 64
#define PBSZ (64 * TSTRIDE)                         // 9216
#define HBSZ (256 * TSTRIDE)                        // 36864
#define OFF_P0 0
#define OFF_P1 PBSZ
#define OFF_H0 (2 * PBSZ)                           // 18432
#define OFF_H1 (OFF_H0 + HBSZ)                      // 55296
#define OFF_SEG (OFF_H1 + HBSZ)                     // 92160, 8 KB packed
#define OFF_ES1 (OFF_SEG + NN * 4)                  // 100352
#define OFF_ES2 (OFF_ES1 + 256)
#define OFF_INVD (OFF_ES2 + 256)
#define AT_SMEM (OFF_INVD + 256)                    // 101120

__global__ __launch_bounds__(512, 2) void attn_kernel(const int* __restrict__ adj,
                                                      float* __restrict__ out) {
    extern __shared__ char smraw[];
    uint32_t su = smem_u32(smraw);
    uint32_t* sEG = reinterpret_cast<uint32_t*>(smraw + OFF_SEG);
    float* eS1 = reinterpret_cast<float*>(smraw + OFF_ES1);
    float* eS2 = reinterpret_cast<float*>(smraw + OFF_ES2);
    float* invd = reinterpret_cast<float*>(smraw + OFF_INVD);

    int t = threadIdx.x, l = t & 31, w = t >> 5;
    int b = blockIdx.y;
    int i0 = blockIdx.x * ITILE;

    for (int c = t; c < NN; c += 512) sEG[c] = g_edEG[b * NN + c];
    if (t < ITILE) {
        eS1[t] = g_es1[b * NN + i0 + t];
        eS2[t] = g_es2[b * NN + i0 + t];
    }
    __syncthreads();

    // p mapping: 8 threads/row, 8 j each (2 int4 adj quads, 4 uint2 factors)
    int pi = t >> 3, jq = t & 7;
    float E1 = eS1[pi], E2 = eS2[pi];
    const int4* adj_row = reinterpret_cast<const int4*>(
                              adj + ((size_t)b * NN + i0 + pi) * NN) + jq * 2;
    const uint2* sEG2 = reinterpret_cast<const uint2*>(sEG);
    float dreg = 0.f;

    // mma mapping: 2i x 8n warp grid, warp m32 x n32
    int mbase = (w & 1) * 32, nbase = (w >> 1) * 32;
    int a_row = (l & 7) + ((l & 8) ? 8 : 0);
    int a_k = (l & 16) ? 16 : 0;
    int b_row = (l & 7) + ((l & 16) ? 8 : 0);
    int b_k = (l & 8) ? 16 : 0;

    const __half* hsrc = g_hTh + (size_t)b * FF * NN;

    const uint32_t PB[2] = {su + OFF_P0, su + OFF_P1};
    const uint32_t HB[2] = {su + OFF_H0, su + OFF_H1};

    #define AT_HFILL(jc, s)                                                  \
        do {                                                                 \
            _Pragma("unroll")                                                \
            for (int l2 = 0; l2 < 4; l2++) {                                 \
                int e = t + 512 * l2;                                        \
                int fr = e >> 3, sg = e & 7;                                 \
                cp16(HB[s] + fr * TSTRIDE + sg * 16,                         \
                     hsrc + (size_t)fr * NN + (jc) + sg * 8);                \
            }                                                                \
            CP_COMMIT();                                                     \
        } while (0)

    int4 aR[2];
    aR[0] = adj_row[0];
    aR[1] = adj_row[1];
    AT_HFILL(0, 0);

    float acc[2][4][4] = {};

    for (int c = 0; c < CHUNKS; c++) {
        int s = c & 1;
        int jc = c * 64;

        // ---- issue h(c+1) cp.async FIRST (max flight time) ----
        if (c + 1 < CHUNKS) AT_HFILL(jc + 64, s ^ 1);

        // ---- p(c) from prefetched adj regs (packed factor loads) ----
        {
            uint32_t pk[4];
            int jb2 = (jc >> 1) + jq * 4;   // uint2 index (pairs of packed u32)
            #pragma unroll
            for (int q = 0; q < 2; q++) {
                int4 av = aR[q];
                uint2 ua = sEG2[jb2 + q * 2];
                uint2 ub = sEG2[jb2 + q * 2 + 1];
                float2 f0 = __half22float2(*reinterpret_cast<__half2*>(&ua.x));
                float2 f1 = __half22float2(*reinterpret_cast<__half2*>(&ua.y));
                float2 f2 = __half22float2(*reinterpret_cast<__half2*>(&ub.x));
                float2 f3 = __half22float2(*reinterpret_cast<__half2*>(&ub.y));
                float p0 = fmaxf(E1 * f0.x, E2 * f0.y);
                float p1 = fmaxf(E1 * f1.x, E2 * f1.y);
                float p2 = fmaxf(E1 * f2.x, E2 * f2.y);
                float p3 = fmaxf(E1 * f3.x, E2 * f3.y);
                p0 = av.x ? p0 : 0.f;
                p1 = av.y ? p1 : 0.f;
                p2 = av.z ? p2 : 0.f;
                p3 = av.w ? p3 : 0.f;
                __half2 h0 = __floats2half2_rn(p0, p1);
                __half2 h1 = __floats2half2_rn(p2, p3);
                float2 r0 = __half22float2(h0);
                float2 r1 = __half22float2(h1);
                dreg += (r0.x + r0.y) + (r1.x + r1.y);
                pk[q * 2] = *reinterpret_cast<uint32_t*>(&h0);
                pk[q * 2 + 1] = *reinterpret_cast<uint32_t*>(&h1);
            }
            uint32_t pa = PB[s] + pi * TSTRIDE + jq * 16;
            asm volatile("st.shared.v4.b32 [%0], {%1,%2,%3,%4};" ::"r"(pa),
                         "r"(pk[0]), "r"(pk[1]), "r"(pk[2]), "r"(pk[3]) : "memory");
        }
        // ---- prefetch adj(c+1) ----
        if (c + 1 < CHUNKS) {
            aR[0] = adj_row[(c + 1) * 16];
            aR[1] = adj_row[(c + 1) * 16 + 1];
            CP_WAIT1();
        } else {
            CP_WAIT0();
        }
        __syncthreads();

        // ---- f16 tensor-core GEMM on buffers s ----
        #pragma unroll
        for (int kk = 0; kk < 4; kk++) {
            uint32_t bf[2][4];
            #pragma unroll
            for (int g = 0; g < 2; g++)
                ldsm4(bf[g], HB[s] + (nbase + g * 16 + b_row) * TSTRIDE +
                                 kk * 32 + b_k);
            #pragma unroll
            for (int mt = 0; mt < 2; mt++) {
                uint32_t a[4];
                ldsm4(a, PB[s] + (mbase + mt * 16 + a_row) * TSTRIDE +
                             kk * 32 + a_k);
                #pragma unroll
                for (int g = 0; g < 2; g++) {
                    mma_f16(acc[mt][2 * g], a, bf[g][0], bf[g][1]);
                    mma_f16(acc[mt][2 * g + 1], a, bf[g][2], bf[g][3]);
                }
            }
        }
        __syncthreads();
    }

    // ---- denominators (8 threads per row -> shfl over 3 levels) ----
    dreg += __shfl_xor_sync(0xFFFFFFFFu, dreg, 1);
    dreg += __shfl_xor_sync(0xFFFFFFFFu, dreg, 2);
    dreg += __shfl_xor_sync(0xFFFFFFFFu, dreg, 4);
    if ((t & 7) == 0) invd[pi] = (dreg > 0.f) ? (1.f / dreg) : 0.f;
    __syncthreads();

    // ---- epilogue ----
    #pragma unroll
    for (int mt = 0; mt < 2; mt++) {
        int lr = mbase + mt * 16 + (l >> 2);
        float s0 = invd[lr], s1v = invd[lr + 8];
        float* o0 = out + ((size_t)b * NN + i0 + lr) * FF + nbase;
        float* o1 = o0 + (size_t)8 * FF;
        #pragma unroll
        for (int nt = 0; nt < 4; nt++) {
            int cofs = nt * 8 + 2 * (l & 3);
            *reinterpret_cast<float2*>(o0 + cofs) =
                make_float2(acc[mt][nt][0] * s0, acc[mt][nt][1] * s0);
            *reinterpret_cast<float2*>(o1 + cofs) =
                make_float2(acc[mt][nt][2] * s1v, acc[mt][nt][3] * s1v);
        }
    }
}

// ---------------------------------------------------------------------------
extern "C" void kernel_launch(void* const* d_in, const int* in_sizes, int n_in,
                              void* d_out, int out_size) {
    const float* x     = (const float*)d_in[0];  // (B,N,F_in)
    const int*   adj   = (const int*)d_in[1];    // (B,N,N)
    const float* W     = (const float*)d_in[2];  // (F_out,F_in)
    const float* a_src = (const float*)d_in[3];  // (F_out)
    const float* a_dst = (const float*)d_in[4];  // (F_out)
    float* out = (float*)d_out;                  // (B,N,F_out)

    (void)in_sizes; (void)n_in; (void)out_size;

    // w = W^T a (warp-per-k) + W f16 conversion, one kernel
    wvec_cvtw_kernel<<<32, 256>>>(W, a_src, a_dst);
    // scores + x f16 conversion, one kernel
    score_kernel<<<(BB * NN) / 8, 256>>>(x);
    // h_T = W @ x^T (f16 tensor cores, m128xn128, 512 thr, single wave)
    cudaFuncSetAttribute(gemm_h_kernel, cudaFuncAttributeMaxDynamicSharedMemorySize,
                         GH_SMEM);
    gemm_h_kernel<<<dim3(NN / 128, FF / 128, BB), 512, GH_SMEM>>>();
    // fused masked softmax + alpha @ h (R14 two-sync, HFILL-first micro-reorder)
    cudaFuncSetAttribute(attn_kernel, cudaFuncAttributeMaxDynamicSharedMemorySize,
                         AT_SMEM);
    attn_kernel<<<dim3(NN / ITILE, BB), 512, AT_SMEM>>>(adj, out);
}